// round 15
// baseline (speedup 1.0000x reference)
#include <cuda_runtime.h>
#include <math.h>
#include <stdint.h>

#define N_NODES 50000
#define N_EDGES 1600000
#define G 128
#define LG 16
#define PI_F 3.14159265358979323846f

typedef unsigned long long u64;

// ---- scratch (device globals; no allocation allowed) ----
__device__ __align__(16) float g_a[N_NODES * LG];
__device__ __align__(16) float g_b[N_NODES * LG];
__device__ __align__(16) float g_nv[N_NODES * 3 * LG];
__device__ __align__(16) float g_acc_s[N_NODES * LG];
__device__ __align__(16) float g_acc_v[N_NODES * 3 * LG];
__device__ __align__(16) float g_es[N_EDGES * LG];     // es scratch (k2a -> k2b)

__device__ __forceinline__ float siluf(float x) { return x / (1.f + __expf(-x)); }

__device__ __forceinline__ void red4(float* p, float a, float b, float c, float d) {
    asm volatile("red.global.add.v4.f32 [%0], {%1,%2,%3,%4};"
                 :: "l"(p), "f"(a), "f"(b), "f"(c), "f"(d) : "memory");
}

// ---- packed f32x2 helpers ----
__device__ __forceinline__ u64 ffma2(u64 a, u64 b, u64 c) {
    u64 d; asm("fma.rn.f32x2 %0,%1,%2,%3;" : "=l"(d) : "l"(a), "l"(b), "l"(c)); return d;
}
__device__ __forceinline__ u64 mul2(u64 a, u64 b) {
    u64 d; asm("mul.rn.f32x2 %0,%1,%2;" : "=l"(d) : "l"(a), "l"(b)); return d;
}
__device__ __forceinline__ u64 add2(u64 a, u64 b) {
    u64 d; asm("add.rn.f32x2 %0,%1,%2;" : "=l"(d) : "l"(a), "l"(b)); return d;
}
__device__ __forceinline__ u64 pk2(float x, float y) {
    u64 r; asm("mov.b64 %0,{%1,%2};" : "=l"(r) : "f"(x), "f"(y)); return r;
}
__device__ __forceinline__ float2 upk(u64 a) {
    float lo, hi; asm("mov.b64 {%0,%1},%2;" : "=f"(lo), "=f"(hi) : "l"(a));
    return make_float2(lo, hi);
}

// ============================================================================
// Kernel 1: node input projections + accumulator zeroing (EXACT R8/R14 version)
// ============================================================================
#define WPAD 130
#define K1_TILES ((N_NODES + 31) / 32)
#define K1_BLOCKS 592

__global__ void __launch_bounds__(256) k_node_in(
    const float* __restrict__ node_s, const float* __restrict__ node_v,
    const float* __restrict__ ns_w, const float* __restrict__ ns_b,
    const float* __restrict__ nv_w, const float* __restrict__ en_w,
    const float* __restrict__ en_b)
{
    __shared__ __align__(16) float s_wsT[16 * WPAD];
    __shared__ __align__(16) float s_wvT[16 * WPAD];
    __shared__ __align__(16) float s_en[512];
    __shared__ float s_sns[32 * 16];
    __shared__ float s_nsb[16], s_enb[16];

    int t = threadIdx.x;

    {
        float4* as4 = (float4*)g_acc_s;
        float4* av4 = (float4*)g_acc_v;
        int idx = blockIdx.x * 256 + t;
        int stride = K1_BLOCKS * 256;
        for (int i = idx; i < 200000; i += stride) as4[i] = make_float4(0.f, 0.f, 0.f, 0.f);
        for (int i = idx; i < 600000; i += stride) av4[i] = make_float4(0.f, 0.f, 0.f, 0.f);
    }

    for (int i = t; i < 2048; i += 256) {
        int gg = i >> 4, j = i & 15;
        s_wsT[j * WPAD + gg] = ns_w[i];
        s_wvT[j * WPAD + gg] = nv_w[i];
    }
    for (int i = t; i < 512; i += 256) s_en[i] = en_w[i];
    if (t < 16) { s_nsb[t] = ns_b[t]; s_enb[t] = en_b[t]; }
    __syncthreads();

    int j = t & 7, slot = t >> 3;
    const float2* wsA = (const float2*)(s_wsT + j * WPAD);
    const float2* wsB = (const float2*)(s_wsT + (j + 8) * WPAD);
    const float2* wvA = (const float2*)(s_wvT + j * WPAD);
    const float2* wvB = (const float2*)(s_wvT + (j + 8) * WPAD);

    for (int tile = blockIdx.x; tile < K1_TILES; tile += K1_BLOCKS) {
        int n = tile * 32 + slot;
        bool ok = (n < N_NODES);

        if (ok) {
            {
                const float4* r4 = (const float4*)(node_s + (size_t)n * 128);
                float aA0 = 0.f, aA1 = 0.f, aB0 = 0.f, aB1 = 0.f;
                #pragma unroll 8
                for (int qq = 0; qq < 32; qq++) {
                    float4 r = __ldg(r4 + qq);
                    float2 wa = wsA[2 * qq], wb = wsA[2 * qq + 1];
                    float2 wc = wsB[2 * qq], wd = wsB[2 * qq + 1];
                    aA0 += r.x * wa.x + r.y * wa.y; aA1 += r.z * wb.x + r.w * wb.y;
                    aB0 += r.x * wc.x + r.y * wc.y; aB1 += r.z * wd.x + r.w * wd.y;
                }
                s_sns[slot * 16 + j]     = siluf(aA0 + aA1 + s_nsb[j]);
                s_sns[slot * 16 + j + 8] = siluf(aB0 + aB1 + s_nsb[j + 8]);
            }
            {
                const float4* v0 = (const float4*)(node_v + (size_t)n * 384);
                const float4* v1 = v0 + 32;
                const float4* v2 = v0 + 64;
                float a0A = 0.f, a1A = 0.f, a2A = 0.f;
                float a0B = 0.f, a1B = 0.f, a2B = 0.f;
                #pragma unroll 8
                for (int qq = 0; qq < 32; qq++) {
                    float2 wa = wvA[2 * qq], wb = wvA[2 * qq + 1];
                    float2 wc = wvB[2 * qq], wd = wvB[2 * qq + 1];
                    float4 r0 = __ldg(v0 + qq), r1 = __ldg(v1 + qq), r2 = __ldg(v2 + qq);
                    a0A += r0.x * wa.x + r0.y * wa.y + r0.z * wb.x + r0.w * wb.y;
                    a1A += r1.x * wa.x + r1.y * wa.y + r1.z * wb.x + r1.w * wb.y;
                    a2A += r2.x * wa.x + r2.y * wa.y + r2.z * wb.x + r2.w * wb.y;
                    a0B += r0.x * wc.x + r0.y * wc.y + r0.z * wd.x + r0.w * wd.y;
                    a1B += r1.x * wc.x + r1.y * wc.y + r1.z * wd.x + r1.w * wd.y;
                    a2B += r2.x * wc.x + r2.y * wc.y + r2.z * wd.x + r2.w * wd.y;
                }
                g_nv[(size_t)n * 48 + j]          = a0A;
                g_nv[(size_t)n * 48 + 16 + j]     = a1A;
                g_nv[(size_t)n * 48 + 32 + j]     = a2A;
                g_nv[(size_t)n * 48 + j + 8]      = a0B;
                g_nv[(size_t)n * 48 + 16 + j + 8] = a1B;
                g_nv[(size_t)n * 48 + 32 + j + 8] = a2B;
            }
        }
        __syncthreads();

        if (ok) {
            float aA = 0.f, bA = s_enb[j];
            float aB = 0.f, bB = s_enb[j + 8];
            #pragma unroll
            for (int k = 0; k < 16; k++) {
                float x = s_sns[slot * 16 + k];
                aA += x * s_en[k * 16 + j];
                bA += x * s_en[(16 + k) * 16 + j];
                aB += x * s_en[k * 16 + j + 8];
                bB += x * s_en[(16 + k) * 16 + j + 8];
            }
            g_a[(size_t)n * 16 + j]     = aA;
            g_b[(size_t)n * 16 + j]     = bA;
            g_a[(size_t)n * 16 + j + 8] = aB;
            g_b[(size_t)n * 16 + j + 8] = bB;
        }
        __syncthreads();
    }
}

// ============================================================================
// Kernel 2a: edge SCALAR chain — gathers, tm/h/gt matvecs, es; writes out_es,
// scatters acc_s, stores es to g_es. Lower live state -> higher occupancy.
// ============================================================================
#define NE 4

#define Q_MATVEC(Y, X, SW, Q)                                                \
    {                                                                        \
        _Pragma("unroll")                                                    \
        for (int k = 0; k < 16; k++) {                                       \
            ulonglong2 w = ((const ulonglong2*)((SW) + k * 16))[Q];          \
            _Pragma("unroll")                                                \
            for (int m = 0; m < NE; m++) {                                   \
                float2 xp = upk(X[m][(k >> 1) & 1]);                         \
                float xs = (k & 1) ? xp.y : xp.x;                            \
                float xk = __shfl_sync(0xffffffffu, xs, k >> 2, 4);          \
                u64 xx = pk2(xk, xk);                                        \
                Y[m][0] = ffma2(xx, w.x, Y[m][0]);                           \
                Y[m][1] = ffma2(xx, w.y, Y[m][1]);                           \
            }                                                                \
        }                                                                    \
    }

__global__ void __launch_bounds__(128) k_edge_a(
    const float* __restrict__ edge_s, const float* __restrict__ dist,
    const int* __restrict__ src,      const int* __restrict__ dst,
    const float* __restrict__ tp_w, const float* __restrict__ tp_b,
    const float* __restrict__ g1w,  const float* __restrict__ g1b,
    const float* __restrict__ g2w,  const float* __restrict__ g2b,
    float* __restrict__ out_es)
{
    __shared__ __align__(16) float s_tp[256], s_g1[256], s_g2[256];
    __shared__ __align__(16) float s_tpb[16], s_g1b[16], s_g2b[16];
    int t = threadIdx.x;
    for (int i = t; i < 256; i += 128) { s_tp[i] = tp_w[i]; s_g1[i] = g1w[i]; s_g2[i] = g2w[i]; }
    if (t < 16) { s_tpb[t] = tp_b[t]; s_g1b[t] = g1b[t]; s_g2b[t] = g2b[t]; }
    __syncthreads();

    int q = t & 3;
    int slot = t >> 2;
    int eb = blockIdx.x * 128 + slot;

    int sa[NE], da[NE];
    float ddv[NE];
    #pragma unroll
    for (int m = 0; m < NE; m++) {
        int e = eb + 32 * m;
        sa[m] = src[e]; da[m] = dst[e]; ddv[m] = dist[e];
    }

    u64 esl[NE][2];
    #pragma unroll
    for (int m = 0; m < NE; m++) {
        ulonglong2 v = ((const ulonglong2*)edge_s)[(size_t)(eb + 32 * m) * 4 + q];
        esl[m][0] = v.x; esl[m][1] = v.y;
    }

    u64 en[NE][2];
    #pragma unroll
    for (int m = 0; m < NE; m++) {
        ulonglong2 va = __ldg((const ulonglong2*)g_a + (size_t)sa[m] * 4 + q);
        ulonglong2 vb = __ldg((const ulonglong2*)g_b + (size_t)da[m] * 4 + q);
        en[m][0] = add2(va.x, vb.x); en[m][1] = add2(va.y, vb.y);
    }

    u64 tm[NE][2];
    {
        ulonglong2 b = ((const ulonglong2*)s_tpb)[q];
        #pragma unroll
        for (int m = 0; m < NE; m++) { tm[m][0] = b.x; tm[m][1] = b.y; }
    }
    Q_MATVEC(tm, esl, s_tp, q);
    #pragma unroll
    for (int m = 0; m < NE; m++) {
        tm[m][0] = mul2(tm[m][0], en[m][0]);
        tm[m][1] = mul2(tm[m][1], en[m][1]);
    }

    u64 h[NE][2];
    {
        ulonglong2 b = ((const ulonglong2*)s_g1b)[q];
        #pragma unroll
        for (int m = 0; m < NE; m++) { h[m][0] = b.x; h[m][1] = b.y; }
    }
    Q_MATVEC(h, tm, s_g1, q);
    #pragma unroll
    for (int m = 0; m < NE; m++) {
        float2 a = upk(h[m][0]), b = upk(h[m][1]);
        h[m][0] = pk2(siluf(a.x), siluf(a.y));
        h[m][1] = pk2(siluf(b.x), siluf(b.y));
    }

    u64 gt[NE][2];
    {
        ulonglong2 b = ((const ulonglong2*)s_g2b)[q];
        #pragma unroll
        for (int m = 0; m < NE; m++) { gt[m][0] = b.x; gt[m][1] = b.y; }
    }
    Q_MATVEC(gt, h, s_g2, q);

    #pragma unroll
    for (int m = 0; m < NE; m++) {
        float C = 0.5f * (__cosf(PI_F * ddv[m] * 0.1f) + 1.f) * (ddv[m] < 10.f ? 1.f : 0.f);
        float2 tv0 = upk(tm[m][0]), tv1 = upk(tm[m][1]);
        float2 gv0 = upk(gt[m][0]), gv1 = upk(gt[m][1]);
        u64 e0 = pk2(tv0.x * (1.f / (1.f + __expf(-gv0.x))) * C,
                     tv0.y * (1.f / (1.f + __expf(-gv0.y))) * C);
        u64 e1 = pk2(tv1.x * (1.f / (1.f + __expf(-gv1.x))) * C,
                     tv1.y * (1.f / (1.f + __expf(-gv1.y))) * C);
        size_t idx = (size_t)(eb + 32 * m) * 4 + q;
        ulonglong2 o;
        o.x = add2(e0, esl[m][0]);
        o.y = add2(e1, esl[m][1]);
        ((ulonglong2*)out_es)[idx] = o;
        ulonglong2 sv; sv.x = e0; sv.y = e1;
        ((ulonglong2*)g_es)[idx] = sv;
        float2 a = upk(e0), b = upk(e1);
        red4(g_acc_s + (size_t)da[m] * 16 + q * 4, a.x, a.y, b.x, b.y);
    }
}

// ============================================================================
// Kernel 2b: edge VECTOR chain — reloads es, ter matvec, vector updates,
// out_ev + acc_v scatter.
// ============================================================================
__global__ void __launch_bounds__(128) k_edge_b(
    const float* __restrict__ edge_v, const float* __restrict__ dist,
    const float* __restrict__ vctr,
    const int* __restrict__ src,      const int* __restrict__ dst,
    const float* __restrict__ tvw,  const float* __restrict__ tvb,
    float* __restrict__ out_ev)
{
    __shared__ __align__(16) float s_tv[768];
    __shared__ __align__(16) float s_tvb[48];
    int t = threadIdx.x;
    for (int i = t; i < 768; i += 128) s_tv[i] = tvw[i];
    if (t < 48) s_tvb[t] = tvb[t];
    __syncthreads();

    int q = t & 3;
    int slot = t >> 2;
    int eb = blockIdx.x * 128 + slot;

    int sa[NE], da[NE];
    float Cv[NE];
    #pragma unroll
    for (int m = 0; m < NE; m++) {
        int e = eb + 32 * m;
        sa[m] = src[e]; da[m] = dst[e];
        float dd = dist[e];
        Cv[m] = 0.5f * (__cosf(PI_F * dd * 0.1f) + 1.f) * (dd < 10.f ? 1.f : 0.f);
    }

    u64 es[NE][2];
    #pragma unroll
    for (int m = 0; m < NE; m++) {
        ulonglong2 v = ((const ulonglong2*)g_es)[(size_t)(eb + 32 * m) * 4 + q];
        es[m][0] = v.x; es[m][1] = v.y;
    }

    u64 ter[NE][6];
    {
        ulonglong2 w0 = ((const ulonglong2*)(s_tvb))[q];
        ulonglong2 w1 = ((const ulonglong2*)(s_tvb + 16))[q];
        ulonglong2 w2 = ((const ulonglong2*)(s_tvb + 32))[q];
        #pragma unroll
        for (int m = 0; m < NE; m++) {
            ter[m][0] = w0.x; ter[m][1] = w0.y;
            ter[m][2] = w1.x; ter[m][3] = w1.y;
            ter[m][4] = w2.x; ter[m][5] = w2.y;
        }
    }
    #pragma unroll
    for (int k = 0; k < 16; k++) {
        ulonglong2 wt = ((const ulonglong2*)(s_tv + k * 48))[q];
        ulonglong2 we = ((const ulonglong2*)(s_tv + k * 48 + 16))[q];
        ulonglong2 wr = ((const ulonglong2*)(s_tv + k * 48 + 32))[q];
        #pragma unroll
        for (int m = 0; m < NE; m++) {
            float2 xp = upk(es[m][(k >> 1) & 1]);
            float xs = (k & 1) ? xp.y : xp.x;
            float xk = __shfl_sync(0xffffffffu, xs, k >> 2, 4);
            u64 xx = pk2(xk, xk);
            ter[m][0] = ffma2(xx, wt.x, ter[m][0]);
            ter[m][1] = ffma2(xx, wt.y, ter[m][1]);
            ter[m][2] = ffma2(xx, we.x, ter[m][2]);
            ter[m][3] = ffma2(xx, we.y, ter[m][3]);
            ter[m][4] = ffma2(xx, wr.x, ter[m][4]);
            ter[m][5] = ffma2(xx, wr.y, ter[m][5]);
        }
    }
    #pragma unroll
    for (int m = 0; m < NE; m++) {
        u64 CC = pk2(Cv[m], Cv[m]);
        #pragma unroll
        for (int i = 0; i < 6; i++) ter[m][i] = mul2(ter[m][i], CC);
    }

    #pragma unroll
    for (int x = 0; x < 3; x++) {
        #pragma unroll
        for (int m = 0; m < NE; m++) {
            int e = eb + 32 * m;
            float vc = vctr[(size_t)e * 3 + x];
            u64 vx = pk2(vc, vc);
            ulonglong2 ev = ((const ulonglong2*)(edge_v + (size_t)e * 48 + x * 16))[q];
            ulonglong2 nv = __ldg((const ulonglong2*)(g_nv + (size_t)sa[m] * 48 + x * 16) + q);
            u64 u0 = ffma2(ev.x, ter[m][0], ffma2(nv.x, ter[m][2], mul2(vx, ter[m][4])));
            u64 u1 = ffma2(ev.y, ter[m][1], ffma2(nv.y, ter[m][3], mul2(vx, ter[m][5])));
            ulonglong2 o; o.x = add2(u0, ev.x); o.y = add2(u1, ev.y);
            ((ulonglong2*)(out_ev + (size_t)e * 48 + x * 16))[q] = o;
            float2 a = upk(u0), b = upk(u1);
            red4(g_acc_v + (size_t)da[m] * 48 + x * 16 + q * 4, a.x, a.y, b.x, b.y);
        }
    }
}

// ============================================================================
// Kernel 3: node epilogue — phase-structured (EXACT R14 version, ~80us)
// ============================================================================
#define K3_NPB 16
__global__ void __launch_bounds__(256) k_node_out(
    const float* __restrict__ node_s, const float* __restrict__ node_v,
    const float* __restrict__ onw,
    const float* __restrict__ w1, const float* __restrict__ b1,
    const float* __restrict__ w2, const float* __restrict__ b2,
    const float* __restrict__ gamma, const float* __restrict__ beta,
    const float* __restrict__ cns, float* __restrict__ out)
{
    __shared__ __align__(16) float s_w1[512], s_w2[2048], s_onw[2048];
    __shared__ float s_b1[16], s_b2[128], s_gam[128], s_bet[128], s_cns[128];
    __shared__ __align__(16) float sacc[16 * 16];
    __shared__ __align__(16) float saccv[16 * 48];
    __shared__ float snvn[16 * 16];
    __shared__ float sh[16 * 16];
    __shared__ float rs1[16][4], rs2[16][4];

    int t = threadIdx.x;
    for (int i = t; i < 512; i += 256) s_w1[i] = w1[i];
    for (int i = t; i < 2048; i += 256) { s_w2[i] = w2[i]; s_onw[i] = onw[i]; }
    if (t < 16) s_b1[t] = b1[t];
    if (t >= 128) {
        int c = t - 128;
        s_b2[c] = b2[c]; s_gam[c] = gamma[c]; s_bet[c] = beta[c]; s_cns[c] = cns[c];
    }

    int n0 = blockIdx.x * K3_NPB;

    sacc[t] = g_acc_s[(size_t)n0 * 16 + t];
    #pragma unroll
    for (int p = 0; p < 3; p++)
        saccv[t + 256 * p] = g_acc_v[(size_t)n0 * 48 + t + 256 * p];
    {
        int nl = t >> 4, l = t & 15;
        size_t bv = (size_t)(n0 + nl) * 48 + l;
        float a = g_nv[bv], b = g_nv[bv + 16], c = g_nv[bv + 32];
        snvn[t] = sqrtf(a * a + b * b + c * c);
    }
    __syncthreads();

    {
        int nl = t >> 4, j = t & 15;
        float acc = s_b1[j];
        #pragma unroll
        for (int k = 0; k < 16; k++) acc += sacc[nl * 16 + k] * s_w1[k * 16 + j];
        #pragma unroll
        for (int k = 0; k < 16; k++) acc += snvn[nl * 16 + k] * s_w1[(16 + k) * 16 + j];
        sh[t] = siluf(acc);
    }
    __syncthreads();

    int grp = t >> 7, tt = t & 127;
    #pragma unroll 1
    for (int it = 0; it < 8; it++) {
        int nl = 2 * it + grp;
        int n = n0 + nl;

        float nsu = s_b2[tt];
        #pragma unroll
        for (int l = 0; l < 16; l++) nsu += sh[nl * 16 + l] * s_w2[l * 128 + tt];
        float xv = nsu + node_s[(size_t)n * 128 + tt];

        float s1 = xv, s2 = xv * xv;
        #pragma unroll
        for (int o = 16; o > 0; o >>= 1) {
            s1 += __shfl_down_sync(0xffffffffu, s1, o);
            s2 += __shfl_down_sync(0xffffffffu, s2, o);
        }
        if ((tt & 31) == 0) { rs1[nl][tt >> 5] = s1; rs2[nl][tt >> 5] = s2; }
        __syncthreads();
        float ts1 = rs1[nl][0] + rs1[nl][1] + rs1[nl][2] + rs1[nl][3];
        float ts2 = rs2[nl][0] + rs2[nl][1] + rs2[nl][2] + rs2[nl][3];
        float mu = ts1 * (1.f / 128.f);
        float var = ts2 * (1.f / 128.f) - mu * mu;
        out[(size_t)n * 128 + tt] = (xv - mu) * rsqrtf(var + 1e-5f) * s_gam[tt] + s_bet[tt];

        float a0 = 0.f, a1 = 0.f, a2 = 0.f;
        #pragma unroll
        for (int l = 0; l < 16; l++) {
            float w = s_onw[l * 128 + tt];
            a0 += saccv[nl * 48 + l] * w;
            a1 += saccv[nl * 48 + 16 + l] * w;
            a2 += saccv[nl * 48 + 32 + l] * w;
        }
        float v0 = a0 + node_v[(size_t)n * 384 + tt];
        float v1 = a1 + node_v[(size_t)n * 384 + 128 + tt];
        float v2 = a2 + node_v[(size_t)n * 384 + 256 + tt];
        float vn = sqrtf(v0 * v0 + v1 * v1 + v2 * v2);
        float sc = s_cns[tt] / (vn + 1e-8f);
        size_t base = 6400000ull + (size_t)n * 384;
        out[base + tt]       = v0 * sc;
        out[base + 128 + tt] = v1 * sc;
        out[base + 256 + tt] = v2 * sc;
    }
}

// ============================================================================
extern "C" void kernel_launch(void* const* d_in, const int* in_sizes, int n_in,
                              void* d_out, int out_size)
{
    const float* node_s  = (const float*)d_in[0];
    const float* node_v  = (const float*)d_in[1];
    const float* edge_s  = (const float*)d_in[2];
    const float* edge_v  = (const float*)d_in[3];
    const float* dist    = (const float*)d_in[4];
    const float* vctr    = (const float*)d_in[5];
    const int*   src     = (const int*)d_in[6];
    const int*   dst     = (const int*)d_in[7];
    const float* ns_in_w = (const float*)d_in[8];
    const float* ns_in_b = (const float*)d_in[9];
    const float* nv_in_w = (const float*)d_in[10];
    const float* en_w    = (const float*)d_in[11];
    const float* en_b    = (const float*)d_in[12];
    const float* tp_w    = (const float*)d_in[13];
    const float* tp_b    = (const float*)d_in[14];
    const float* gate_w1 = (const float*)d_in[15];
    const float* gate_b1 = (const float*)d_in[16];
    const float* gate_w2 = (const float*)d_in[17];
    const float* gate_b2 = (const float*)d_in[18];
    const float* tv_w    = (const float*)d_in[19];
    const float* tv_b    = (const float*)d_in[20];
    const float* out_nv_w= (const float*)d_in[21];
    const float* ons_w1  = (const float*)d_in[22];
    const float* ons_b1  = (const float*)d_in[23];
    const float* ons_w2  = (const float*)d_in[24];
    const float* ons_b2  = (const float*)d_in[25];
    const float* ln_gamma= (const float*)d_in[26];
    const float* ln_beta = (const float*)d_in[27];
    const float* cn_scale= (const float*)d_in[28];

    float* out = (float*)d_out;
    float* out_es = out + 25600000ull;
    float* out_ev = out + 51200000ull;

    k_node_in<<<K1_BLOCKS, 256>>>(node_s, node_v, ns_in_w, ns_in_b, nv_in_w, en_w, en_b);
    k_edge_a<<<N_EDGES / 128, 128>>>(edge_s, dist, src, dst,
                                     tp_w, tp_b, gate_w1, gate_b1, gate_w2, gate_b2,
                                     out_es);
    k_edge_b<<<N_EDGES / 128, 128>>>(edge_v, dist, vctr, src, dst,
                                     tv_w, tv_b, out_ev);
    k_node_out<<<N_NODES / K3_NPB, 256>>>(node_s, node_v, out_nv_w, ons_w1, ons_b1,
                                          ons_w2, ons_b2, ln_gamma, ln_beta, cn_scale, out);
}

// round 16
// speedup vs baseline: 1.1266x; 1.1266x over previous
#include <cuda_runtime.h>
#include <math.h>
#include <stdint.h>

#define N_NODES 50000
#define N_EDGES 1600000
#define G 128
#define LG 16
#define PI_F 3.14159265358979323846f

typedef unsigned long long u64;

// ---- scratch (device globals; no allocation allowed) ----
__device__ __align__(16) float g_a[N_NODES * LG];
__device__ __align__(16) float g_b[N_NODES * LG];
__device__ __align__(16) float g_nv[N_NODES * 3 * LG];
__device__ __align__(16) float g_acc_s[N_NODES * LG];
__device__ __align__(16) float g_acc_v[N_NODES * 3 * LG];

__device__ __forceinline__ float siluf(float x) { return x / (1.f + __expf(-x)); }

__device__ __forceinline__ void red4(float* p, float a, float b, float c, float d) {
    asm volatile("red.global.add.v4.f32 [%0], {%1,%2,%3,%4};"
                 :: "l"(p), "f"(a), "f"(b), "f"(c), "f"(d) : "memory");
}

// ---- packed f32x2 helpers ----
__device__ __forceinline__ u64 ffma2(u64 a, u64 b, u64 c) {
    u64 d; asm("fma.rn.f32x2 %0,%1,%2,%3;" : "=l"(d) : "l"(a), "l"(b), "l"(c)); return d;
}
__device__ __forceinline__ u64 mul2(u64 a, u64 b) {
    u64 d; asm("mul.rn.f32x2 %0,%1,%2;" : "=l"(d) : "l"(a), "l"(b)); return d;
}
__device__ __forceinline__ u64 add2(u64 a, u64 b) {
    u64 d; asm("add.rn.f32x2 %0,%1,%2;" : "=l"(d) : "l"(a), "l"(b)); return d;
}
__device__ __forceinline__ u64 pk2(float x, float y) {
    u64 r; asm("mov.b64 %0,{%1,%2};" : "=l"(r) : "f"(x), "f"(y)); return r;
}
__device__ __forceinline__ float2 upk(u64 a) {
    float lo, hi; asm("mov.b64 {%0,%1},%2;" : "=f"(lo), "=f"(hi) : "l"(a));
    return make_float2(lo, hi);
}

// ============================================================================
// Kernel 1: node input projections + accumulator zeroing (EXACT R8/R14)
// ============================================================================
#define WPAD 130
#define K1_TILES ((N_NODES + 31) / 32)
#define K1_BLOCKS 592

__global__ void __launch_bounds__(256) k_node_in(
    const float* __restrict__ node_s, const float* __restrict__ node_v,
    const float* __restrict__ ns_w, const float* __restrict__ ns_b,
    const float* __restrict__ nv_w, const float* __restrict__ en_w,
    const float* __restrict__ en_b)
{
    __shared__ __align__(16) float s_wsT[16 * WPAD];
    __shared__ __align__(16) float s_wvT[16 * WPAD];
    __shared__ __align__(16) float s_en[512];
    __shared__ float s_sns[32 * 16];
    __shared__ float s_nsb[16], s_enb[16];

    int t = threadIdx.x;

    {
        float4* as4 = (float4*)g_acc_s;
        float4* av4 = (float4*)g_acc_v;
        int idx = blockIdx.x * 256 + t;
        int stride = K1_BLOCKS * 256;
        for (int i = idx; i < 200000; i += stride) as4[i] = make_float4(0.f, 0.f, 0.f, 0.f);
        for (int i = idx; i < 600000; i += stride) av4[i] = make_float4(0.f, 0.f, 0.f, 0.f);
    }

    for (int i = t; i < 2048; i += 256) {
        int gg = i >> 4, j = i & 15;
        s_wsT[j * WPAD + gg] = ns_w[i];
        s_wvT[j * WPAD + gg] = nv_w[i];
    }
    for (int i = t; i < 512; i += 256) s_en[i] = en_w[i];
    if (t < 16) { s_nsb[t] = ns_b[t]; s_enb[t] = en_b[t]; }
    __syncthreads();

    int j = t & 7, slot = t >> 3;
    const float2* wsA = (const float2*)(s_wsT + j * WPAD);
    const float2* wsB = (const float2*)(s_wsT + (j + 8) * WPAD);
    const float2* wvA = (const float2*)(s_wvT + j * WPAD);
    const float2* wvB = (const float2*)(s_wvT + (j + 8) * WPAD);

    for (int tile = blockIdx.x; tile < K1_TILES; tile += K1_BLOCKS) {
        int n = tile * 32 + slot;
        bool ok = (n < N_NODES);

        if (ok) {
            {
                const float4* r4 = (const float4*)(node_s + (size_t)n * 128);
                float aA0 = 0.f, aA1 = 0.f, aB0 = 0.f, aB1 = 0.f;
                #pragma unroll 8
                for (int qq = 0; qq < 32; qq++) {
                    float4 r = __ldg(r4 + qq);
                    float2 wa = wsA[2 * qq], wb = wsA[2 * qq + 1];
                    float2 wc = wsB[2 * qq], wd = wsB[2 * qq + 1];
                    aA0 += r.x * wa.x + r.y * wa.y; aA1 += r.z * wb.x + r.w * wb.y;
                    aB0 += r.x * wc.x + r.y * wc.y; aB1 += r.z * wd.x + r.w * wd.y;
                }
                s_sns[slot * 16 + j]     = siluf(aA0 + aA1 + s_nsb[j]);
                s_sns[slot * 16 + j + 8] = siluf(aB0 + aB1 + s_nsb[j + 8]);
            }
            {
                const float4* v0 = (const float4*)(node_v + (size_t)n * 384);
                const float4* v1 = v0 + 32;
                const float4* v2 = v0 + 64;
                float a0A = 0.f, a1A = 0.f, a2A = 0.f;
                float a0B = 0.f, a1B = 0.f, a2B = 0.f;
                #pragma unroll 8
                for (int qq = 0; qq < 32; qq++) {
                    float2 wa = wvA[2 * qq], wb = wvA[2 * qq + 1];
                    float2 wc = wvB[2 * qq], wd = wvB[2 * qq + 1];
                    float4 r0 = __ldg(v0 + qq), r1 = __ldg(v1 + qq), r2 = __ldg(v2 + qq);
                    a0A += r0.x * wa.x + r0.y * wa.y + r0.z * wb.x + r0.w * wb.y;
                    a1A += r1.x * wa.x + r1.y * wa.y + r1.z * wb.x + r1.w * wb.y;
                    a2A += r2.x * wa.x + r2.y * wa.y + r2.z * wb.x + r2.w * wb.y;
                    a0B += r0.x * wc.x + r0.y * wc.y + r0.z * wd.x + r0.w * wd.y;
                    a1B += r1.x * wc.x + r1.y * wc.y + r1.z * wd.x + r1.w * wd.y;
                    a2B += r2.x * wc.x + r2.y * wc.y + r2.z * wd.x + r2.w * wd.y;
                }
                g_nv[(size_t)n * 48 + j]          = a0A;
                g_nv[(size_t)n * 48 + 16 + j]     = a1A;
                g_nv[(size_t)n * 48 + 32 + j]     = a2A;
                g_nv[(size_t)n * 48 + j + 8]      = a0B;
                g_nv[(size_t)n * 48 + 16 + j + 8] = a1B;
                g_nv[(size_t)n * 48 + 32 + j + 8] = a2B;
            }
        }
        __syncthreads();

        if (ok) {
            float aA = 0.f, bA = s_enb[j];
            float aB = 0.f, bB = s_enb[j + 8];
            #pragma unroll
            for (int k = 0; k < 16; k++) {
                float x = s_sns[slot * 16 + k];
                aA += x * s_en[k * 16 + j];
                bA += x * s_en[(16 + k) * 16 + j];
                aB += x * s_en[k * 16 + j + 8];
                bB += x * s_en[(16 + k) * 16 + j + 8];
            }
            g_a[(size_t)n * 16 + j]     = aA;
            g_b[(size_t)n * 16 + j]     = bA;
            g_a[(size_t)n * 16 + j + 8] = aB;
            g_b[(size_t)n * 16 + j + 8] = bB;
        }
        __syncthreads();
    }
}

// ============================================================================
// Kernel 2: QUAD layout, 4 edges/thread (EXACT R8 version — 287us measured)
// ============================================================================
#define NE 4

#define Q_MATVEC(Y, X, SW, Q)                                                \
    {                                                                        \
        _Pragma("unroll")                                                    \
        for (int k = 0; k < 16; k++) {                                       \
            ulonglong2 w = ((const ulonglong2*)((SW) + k * 16))[Q];          \
            _Pragma("unroll")                                                \
            for (int m = 0; m < NE; m++) {                                   \
                float2 xp = upk(X[m][(k >> 1) & 1]);                         \
                float xs = (k & 1) ? xp.y : xp.x;                            \
                float xk = __shfl_sync(0xffffffffu, xs, k >> 2, 4);          \
                u64 xx = pk2(xk, xk);                                        \
                Y[m][0] = ffma2(xx, w.x, Y[m][0]);                           \
                Y[m][1] = ffma2(xx, w.y, Y[m][1]);                           \
            }                                                                \
        }                                                                    \
    }

__global__ void __launch_bounds__(128, 4) k_edge(
    const float* __restrict__ edge_s, const float* __restrict__ edge_v,
    const float* __restrict__ dist,   const float* __restrict__ vctr,
    const int* __restrict__ src,      const int* __restrict__ dst,
    const float* __restrict__ tp_w, const float* __restrict__ tp_b,
    const float* __restrict__ g1w,  const float* __restrict__ g1b,
    const float* __restrict__ g2w,  const float* __restrict__ g2b,
    const float* __restrict__ tvw,  const float* __restrict__ tvb,
    float* __restrict__ out_es, float* __restrict__ out_ev)
{
    __shared__ __align__(16) float s_tp[256], s_g1[256], s_g2[256], s_tv[768];
    __shared__ __align__(16) float s_tpb[16], s_g1b[16], s_g2b[16], s_tvb[48];
    int t = threadIdx.x;
    for (int i = t; i < 256; i += 128) { s_tp[i] = tp_w[i]; s_g1[i] = g1w[i]; s_g2[i] = g2w[i]; }
    for (int i = t; i < 768; i += 128) s_tv[i] = tvw[i];
    if (t < 16) { s_tpb[t] = tp_b[t]; s_g1b[t] = g1b[t]; s_g2b[t] = g2b[t]; }
    if (t < 48) s_tvb[t] = tvb[t];
    __syncthreads();

    int q = t & 3;
    int slot = t >> 2;
    int eb = blockIdx.x * 128 + slot;

    int sa[NE], da[NE];
    float ddv[NE];
    #pragma unroll
    for (int m = 0; m < NE; m++) {
        int e = eb + 32 * m;
        sa[m] = src[e]; da[m] = dst[e]; ddv[m] = dist[e];
    }

    u64 esl[NE][2];
    #pragma unroll
    for (int m = 0; m < NE; m++) {
        ulonglong2 v = ((const ulonglong2*)edge_s)[(size_t)(eb + 32 * m) * 4 + q];
        esl[m][0] = v.x; esl[m][1] = v.y;
    }

    u64 en[NE][2];
    #pragma unroll
    for (int m = 0; m < NE; m++) {
        ulonglong2 va = __ldg((const ulonglong2*)g_a + (size_t)sa[m] * 4 + q);
        ulonglong2 vb = __ldg((const ulonglong2*)g_b + (size_t)da[m] * 4 + q);
        en[m][0] = add2(va.x, vb.x); en[m][1] = add2(va.y, vb.y);
    }

    u64 tm[NE][2];
    {
        ulonglong2 b = ((const ulonglong2*)s_tpb)[q];
        #pragma unroll
        for (int m = 0; m < NE; m++) { tm[m][0] = b.x; tm[m][1] = b.y; }
    }
    Q_MATVEC(tm, esl, s_tp, q);
    #pragma unroll
    for (int m = 0; m < NE; m++) {
        tm[m][0] = mul2(tm[m][0], en[m][0]);
        tm[m][1] = mul2(tm[m][1], en[m][1]);
    }

    u64 h[NE][2];
    {
        ulonglong2 b = ((const ulonglong2*)s_g1b)[q];
        #pragma unroll
        for (int m = 0; m < NE; m++) { h[m][0] = b.x; h[m][1] = b.y; }
    }
    Q_MATVEC(h, tm, s_g1, q);
    #pragma unroll
    for (int m = 0; m < NE; m++) {
        float2 a = upk(h[m][0]), b = upk(h[m][1]);
        h[m][0] = pk2(siluf(a.x), siluf(a.y));
        h[m][1] = pk2(siluf(b.x), siluf(b.y));
    }

    u64 gt[NE][2];
    {
        ulonglong2 b = ((const ulonglong2*)s_g2b)[q];
        #pragma unroll
        for (int m = 0; m < NE; m++) { gt[m][0] = b.x; gt[m][1] = b.y; }
    }
    Q_MATVEC(gt, h, s_g2, q);

    float Cv[NE];
    #pragma unroll
    for (int m = 0; m < NE; m++)
        Cv[m] = 0.5f * (__cosf(PI_F * ddv[m] * 0.1f) + 1.f) * (ddv[m] < 10.f ? 1.f : 0.f);

    u64 es[NE][2];
    #pragma unroll
    for (int m = 0; m < NE; m++) {
        float2 tv0 = upk(tm[m][0]), tv1 = upk(tm[m][1]);
        float2 gv0 = upk(gt[m][0]), gv1 = upk(gt[m][1]);
        es[m][0] = pk2(tv0.x * (1.f / (1.f + __expf(-gv0.x))) * Cv[m],
                       tv0.y * (1.f / (1.f + __expf(-gv0.y))) * Cv[m]);
        es[m][1] = pk2(tv1.x * (1.f / (1.f + __expf(-gv1.x))) * Cv[m],
                       tv1.y * (1.f / (1.f + __expf(-gv1.y))) * Cv[m]);
        ulonglong2 o;
        o.x = add2(es[m][0], esl[m][0]);
        o.y = add2(es[m][1], esl[m][1]);
        ((ulonglong2*)out_es)[(size_t)(eb + 32 * m) * 4 + q] = o;
        float2 a = upk(es[m][0]), b = upk(es[m][1]);
        red4(g_acc_s + (size_t)da[m] * 16 + q * 4, a.x, a.y, b.x, b.y);
    }

    u64 ter[NE][6];
    {
        ulonglong2 w0 = ((const ulonglong2*)(s_tvb))[q];
        ulonglong2 w1 = ((const ulonglong2*)(s_tvb + 16))[q];
        ulonglong2 w2 = ((const ulonglong2*)(s_tvb + 32))[q];
        #pragma unroll
        for (int m = 0; m < NE; m++) {
            ter[m][0] = w0.x; ter[m][1] = w0.y;
            ter[m][2] = w1.x; ter[m][3] = w1.y;
            ter[m][4] = w2.x; ter[m][5] = w2.y;
        }
    }
    #pragma unroll
    for (int k = 0; k < 16; k++) {
        ulonglong2 wt = ((const ulonglong2*)(s_tv + k * 48))[q];
        ulonglong2 we = ((const ulonglong2*)(s_tv + k * 48 + 16))[q];
        ulonglong2 wr = ((const ulonglong2*)(s_tv + k * 48 + 32))[q];
        #pragma unroll
        for (int m = 0; m < NE; m++) {
            float2 xp = upk(es[m][(k >> 1) & 1]);
            float xs = (k & 1) ? xp.y : xp.x;
            float xk = __shfl_sync(0xffffffffu, xs, k >> 2, 4);
            u64 xx = pk2(xk, xk);
            ter[m][0] = ffma2(xx, wt.x, ter[m][0]);
            ter[m][1] = ffma2(xx, wt.y, ter[m][1]);
            ter[m][2] = ffma2(xx, we.x, ter[m][2]);
            ter[m][3] = ffma2(xx, we.y, ter[m][3]);
            ter[m][4] = ffma2(xx, wr.x, ter[m][4]);
            ter[m][5] = ffma2(xx, wr.y, ter[m][5]);
        }
    }
    #pragma unroll
    for (int m = 0; m < NE; m++) {
        u64 CC = pk2(Cv[m], Cv[m]);
        #pragma unroll
        for (int i = 0; i < 6; i++) ter[m][i] = mul2(ter[m][i], CC);
    }

    #pragma unroll
    for (int x = 0; x < 3; x++) {
        #pragma unroll
        for (int m = 0; m < NE; m++) {
            int e = eb + 32 * m;
            float vc = vctr[(size_t)e * 3 + x];
            u64 vx = pk2(vc, vc);
            ulonglong2 ev = ((const ulonglong2*)(edge_v + (size_t)e * 48 + x * 16))[q];
            ulonglong2 nv = __ldg((const ulonglong2*)(g_nv + (size_t)sa[m] * 48 + x * 16) + q);
            u64 u0 = ffma2(ev.x, ter[m][0], ffma2(nv.x, ter[m][2], mul2(vx, ter[m][4])));
            u64 u1 = ffma2(ev.y, ter[m][1], ffma2(nv.y, ter[m][3], mul2(vx, ter[m][5])));
            ulonglong2 o; o.x = add2(u0, ev.x); o.y = add2(u1, ev.y);
            ((ulonglong2*)(out_ev + (size_t)e * 48 + x * 16))[q] = o;
            float2 a = upk(u0), b = upk(u1);
            red4(g_acc_v + (size_t)da[m] * 48 + x * 16 + q * 4, a.x, a.y, b.x, b.y);
        }
    }
}

// ============================================================================
// Kernel 3: node epilogue — phase-structured; phase C now processes 2 nodes
// per thread per iteration (shared weight LDS), 4 iterations.
// ============================================================================
#define K3_NPB 16
__global__ void __launch_bounds__(256) k_node_out(
    const float* __restrict__ node_s, const float* __restrict__ node_v,
    const float* __restrict__ onw,
    const float* __restrict__ w1, const float* __restrict__ b1,
    const float* __restrict__ w2, const float* __restrict__ b2,
    const float* __restrict__ gamma, const float* __restrict__ beta,
    const float* __restrict__ cns, float* __restrict__ out)
{
    __shared__ __align__(16) float s_w1[512], s_w2[2048], s_onw[2048];
    __shared__ float s_b1[16], s_b2[128], s_gam[128], s_bet[128], s_cns[128];
    __shared__ __align__(16) float sacc[16 * 16];
    __shared__ __align__(16) float saccv[16 * 48];
    __shared__ float snvn[16 * 16];
    __shared__ float sh[16 * 16];
    __shared__ float rs1[16][4], rs2[16][4];

    int t = threadIdx.x;
    for (int i = t; i < 512; i += 256) s_w1[i] = w1[i];
    for (int i = t; i < 2048; i += 256) { s_w2[i] = w2[i]; s_onw[i] = onw[i]; }
    if (t < 16) s_b1[t] = b1[t];
    if (t >= 128) {
        int c = t - 128;
        s_b2[c] = b2[c]; s_gam[c] = gamma[c]; s_bet[c] = beta[c]; s_cns[c] = cns[c];
    }

    int n0 = blockIdx.x * K3_NPB;

    // ---- Phase A: bulk-load scratch ----
    sacc[t] = g_acc_s[(size_t)n0 * 16 + t];
    #pragma unroll
    for (int p = 0; p < 3; p++)
        saccv[t + 256 * p] = g_acc_v[(size_t)n0 * 48 + t + 256 * p];
    {
        int nl = t >> 4, l = t & 15;
        size_t bv = (size_t)(n0 + nl) * 48 + l;
        float a = g_nv[bv], b = g_nv[bv + 16], c = g_nv[bv + 32];
        snvn[t] = sqrtf(a * a + b * b + c * c);
    }
    __syncthreads();

    // ---- Phase B: sh for all 16 nodes ----
    {
        int nl = t >> 4, j = t & 15;
        float acc = s_b1[j];
        #pragma unroll
        for (int k = 0; k < 16; k++) acc += sacc[nl * 16 + k] * s_w1[k * 16 + j];
        #pragma unroll
        for (int k = 0; k < 16; k++) acc += snvn[nl * 16 + k] * s_w1[(16 + k) * 16 + j];
        sh[t] = siluf(acc);
    }
    __syncthreads();

    // ---- Phase C: 4 iterations; each 128-group handles 2 nodes, weights
    //      loaded once per (l, tt) and reused for both nodes ----
    int grp = t >> 7, tt = t & 127;
    #pragma unroll 1
    for (int it = 0; it < 4; it++) {
        int nlA = 4 * it + 2 * grp;
        int nlB = nlA + 1;
        int nA = n0 + nlA, nB = n0 + nlB;

        float nsuA = s_b2[tt], nsuB = nsuA;
        #pragma unroll
        for (int l = 0; l < 16; l++) {
            float w = s_w2[l * 128 + tt];
            nsuA += sh[nlA * 16 + l] * w;
            nsuB += sh[nlB * 16 + l] * w;
        }
        float xvA = nsuA + node_s[(size_t)nA * 128 + tt];
        float xvB = nsuB + node_s[(size_t)nB * 128 + tt];

        float s1A = xvA, s2A = xvA * xvA;
        float s1B = xvB, s2B = xvB * xvB;
        #pragma unroll
        for (int o = 16; o > 0; o >>= 1) {
            s1A += __shfl_down_sync(0xffffffffu, s1A, o);
            s2A += __shfl_down_sync(0xffffffffu, s2A, o);
            s1B += __shfl_down_sync(0xffffffffu, s1B, o);
            s2B += __shfl_down_sync(0xffffffffu, s2B, o);
        }
        if ((tt & 31) == 0) {
            rs1[nlA][tt >> 5] = s1A; rs2[nlA][tt >> 5] = s2A;
            rs1[nlB][tt >> 5] = s1B; rs2[nlB][tt >> 5] = s2B;
        }
        __syncthreads();
        {
            float ts1 = rs1[nlA][0] + rs1[nlA][1] + rs1[nlA][2] + rs1[nlA][3];
            float ts2 = rs2[nlA][0] + rs2[nlA][1] + rs2[nlA][2] + rs2[nlA][3];
            float mu = ts1 * (1.f / 128.f);
            float var = ts2 * (1.f / 128.f) - mu * mu;
            out[(size_t)nA * 128 + tt] = (xvA - mu) * rsqrtf(var + 1e-5f) * s_gam[tt] + s_bet[tt];
        }
        {
            float ts1 = rs1[nlB][0] + rs1[nlB][1] + rs1[nlB][2] + rs1[nlB][3];
            float ts2 = rs2[nlB][0] + rs2[nlB][1] + rs2[nlB][2] + rs2[nlB][3];
            float mu = ts1 * (1.f / 128.f);
            float var = ts2 * (1.f / 128.f) - mu * mu;
            out[(size_t)nB * 128 + tt] = (xvB - mu) * rsqrtf(var + 1e-5f) * s_gam[tt] + s_bet[tt];
        }

        // vector matvecs for both nodes, shared onw LDS
        float a0A = 0.f, a1A = 0.f, a2A = 0.f;
        float a0B = 0.f, a1B = 0.f, a2B = 0.f;
        #pragma unroll
        for (int l = 0; l < 16; l++) {
            float w = s_onw[l * 128 + tt];
            a0A += saccv[nlA * 48 + l] * w;
            a1A += saccv[nlA * 48 + 16 + l] * w;
            a2A += saccv[nlA * 48 + 32 + l] * w;
            a0B += saccv[nlB * 48 + l] * w;
            a1B += saccv[nlB * 48 + 16 + l] * w;
            a2B += saccv[nlB * 48 + 32 + l] * w;
        }
        {
            float v0 = a0A + node_v[(size_t)nA * 384 + tt];
            float v1 = a1A + node_v[(size_t)nA * 384 + 128 + tt];
            float v2 = a2A + node_v[(size_t)nA * 384 + 256 + tt];
            float vn = sqrtf(v0 * v0 + v1 * v1 + v2 * v2);
            float sc = s_cns[tt] / (vn + 1e-8f);
            size_t base = 6400000ull + (size_t)nA * 384;
            out[base + tt]       = v0 * sc;
            out[base + 128 + tt] = v1 * sc;
            out[base + 256 + tt] = v2 * sc;
        }
        {
            float v0 = a0B + node_v[(size_t)nB * 384 + tt];
            float v1 = a1B + node_v[(size_t)nB * 384 + 128 + tt];
            float v2 = a2B + node_v[(size_t)nB * 384 + 256 + tt];
            float vn = sqrtf(v0 * v0 + v1 * v1 + v2 * v2);
            float sc = s_cns[tt] / (vn + 1e-8f);
            size_t base = 6400000ull + (size_t)nB * 384;
            out[base + tt]       = v0 * sc;
            out[base + 128 + tt] = v1 * sc;
            out[base + 256 + tt] = v2 * sc;
        }
    }
}

// ============================================================================
extern "C" void kernel_launch(void* const* d_in, const int* in_sizes, int n_in,
                              void* d_out, int out_size)
{
    const float* node_s  = (const float*)d_in[0];
    const float* node_v  = (const float*)d_in[1];
    const float* edge_s  = (const float*)d_in[2];
    const float* edge_v  = (const float*)d_in[3];
    const float* dist    = (const float*)d_in[4];
    const float* vctr    = (const float*)d_in[5];
    const int*   src     = (const int*)d_in[6];
    const int*   dst     = (const int*)d_in[7];
    const float* ns_in_w = (const float*)d_in[8];
    const float* ns_in_b = (const float*)d_in[9];
    const float* nv_in_w = (const float*)d_in[10];
    const float* en_w    = (const float*)d_in[11];
    const float* en_b    = (const float*)d_in[12];
    const float* tp_w    = (const float*)d_in[13];
    const float* tp_b    = (const float*)d_in[14];
    const float* gate_w1 = (const float*)d_in[15];
    const float* gate_b1 = (const float*)d_in[16];
    const float* gate_w2 = (const float*)d_in[17];
    const float* gate_b2 = (const float*)d_in[18];
    const float* tv_w    = (const float*)d_in[19];
    const float* tv_b    = (const float*)d_in[20];
    const float* out_nv_w= (const float*)d_in[21];
    const float* ons_w1  = (const float*)d_in[22];
    const float* ons_b1  = (const float*)d_in[23];
    const float* ons_w2  = (const float*)d_in[24];
    const float* ons_b2  = (const float*)d_in[25];
    const float* ln_gamma= (const float*)d_in[26];
    const float* ln_beta = (const float*)d_in[27];
    const float* cn_scale= (const float*)d_in[28];

    float* out = (float*)d_out;
    float* out_es = out + 25600000ull;
    float* out_ev = out + 51200000ull;

    k_node_in<<<K1_BLOCKS, 256>>>(node_s, node_v, ns_in_w, ns_in_b, nv_in_w, en_w, en_b);
    k_edge<<<N_EDGES / 128, 128>>>(edge_s, edge_v, dist, vctr, src, dst,
                                   tp_w, tp_b, gate_w1, gate_b1, gate_w2, gate_b2,
                                   tv_w, tv_b, out_es, out_ev);
    k_node_out<<<N_NODES / K3_NPB, 256>>>(node_s, node_v, out_nv_w, ons_w1, ons_b1,
                                          ons_w2, ons_b2, ln_gamma, ln_beta, cn_scale, out);
}